// round 1
// baseline (speedup 1.0000x reference)
#include <cuda_runtime.h>
#include <math.h>

// Problem constants (fixed by setup_inputs)
#define NN 4096          // n = 64*64
#define DD 21            // classes
#define BSZ 4            // batch
#define K_CH 512         // k chunk staged in smem
#define BLOCK 128        // 4 warps
#define ROWS_PER_WARP 8  // 4 mm-groups * 2 rows/thread
#define ROWS_PER_BLOCK 32
#define NITERS 5

typedef unsigned long long u64;

// Ping-pong softmax buffers (scratch via __device__ globals — no allocation)
__device__ float g_QA[BSZ * DD * NN];
__device__ float g_QB[BSZ * DD * NN];

__device__ __forceinline__ void ffma2(u64 &acc, u64 a, u64 b) {
    asm("fma.rn.f32x2 %0, %1, %2, %0;" : "+l"(acc) : "l"(a), "l"(b));
}
__device__ __forceinline__ void fadd2(u64 &acc, u64 a) {
    asm("add.rn.f32x2 %0, %1, %0;" : "+l"(acc) : "l"(a));
}
__device__ __forceinline__ float lo32(u64 v) {
    return __uint_as_float((unsigned)(v & 0xffffffffull));
}
__device__ __forceinline__ float hi32(u64 v) {
    return __uint_as_float((unsigned)(v >> 32));
}

// Initial softmax over class dim: g_QA = softmax(seg, axis=d)
__global__ void softmax0_kernel(const float* __restrict__ seg) {
    int idx = blockIdx.x * blockDim.x + threadIdx.x;
    if (idx >= BSZ * NN) return;
    int b = idx >> 12;
    int n = idx & (NN - 1);
    const float* p = seg + (size_t)b * DD * NN + n;
    float v[DD];
    float mx = -3.4e38f;
#pragma unroll
    for (int d = 0; d < DD; d++) { v[d] = p[(size_t)d * NN]; mx = fmaxf(mx, v[d]); }
    float s = 0.f;
#pragma unroll
    for (int d = 0; d < DD; d++) { v[d] = __expf(v[d] - mx); s += v[d]; }
    float si = 1.0f / s;
    float* q = g_QA + (size_t)b * DD * NN + n;
#pragma unroll
    for (int d = 0; d < DD; d++) q[(size_t)d * NN] = v[d] * si;
}

// One mean-field iteration, fully fused:
//   acc[e] = sum_n Q[e,n]*W[m,n];  rs = sum_n W[m,n]
//   sd[e]  = acc[e]/rs
//   out[d] = seg[d,m] - sum_e weights[d,e]*sd[e]
//   if !last: Qout[d,m] = softmax_d(out)   else: d_out = out
__global__ __launch_bounds__(BLOCK, 3)
void crf_main(const float* __restrict__ seg,
              const float* __restrict__ W,
              const float* __restrict__ wts,
              float* __restrict__ out,
              int qsel, int last)
{
    __shared__ __align__(16) float q_s[DD * K_CH];
    __shared__ float w_s[DD * DD];

    const float* Qin  = qsel ? g_QB : g_QA;
    float*       Qout = qsel ? g_QA : g_QB;

    int tid  = threadIdx.x;
    int b    = blockIdx.x >> 7;          // 128 blocks per batch
    int mtil = blockIdx.x & 127;
    int warp = tid >> 5;
    int lane = tid & 31;
    int kk   = lane & 7;                 // k sub-lane (8)
    int mm   = lane >> 3;                // m group (4)
    int m0   = mtil * ROWS_PER_BLOCK + warp * ROWS_PER_WARP + mm * 2;

    for (int i = tid; i < DD * DD; i += BLOCK) w_s[i] = wts[i];

    u64 acc[DD + 1][2];
#pragma unroll
    for (int d = 0; d <= DD; d++) { acc[d][0] = 0ull; acc[d][1] = 0ull; }

    const u64* w0p = (const u64*)(W + ((size_t)(b * NN + m0)) * NN);
    const u64* w1p = w0p + (NN / 2);     // row m0+1
    const float* qg = Qin + (size_t)b * DD * NN;

    for (int kc = 0; kc < NN; kc += K_CH) {
        __syncthreads();
        // stage Q[d][kc..kc+K_CH) into smem, coalesced float4
        for (int i = tid; i < DD * (K_CH / 4); i += BLOCK) {
            int d  = i / (K_CH / 4);
            int k4 = (i % (K_CH / 4)) * 4;
            *(float4*)&q_s[d * K_CH + k4] =
                *(const float4*)&qg[(size_t)d * NN + kc + k4];
        }
        __syncthreads();
        const u64* qs2 = (const u64*)q_s;
#pragma unroll 2
        for (int k0 = 0; k0 < K_CH; k0 += 16) {   // warp covers 16 k per step
            int kqi = (k0 >> 1) + kk;
            u64 w0 = w0p[((kc + k0) >> 1) + kk];
            u64 w1 = w1p[((kc + k0) >> 1) + kk];
#pragma unroll
            for (int d = 0; d < DD; d++) {
                u64 q = qs2[d * (K_CH / 2) + kqi];
                ffma2(acc[d][0], q, w0);
                ffma2(acc[d][1], q, w1);
            }
            fadd2(acc[DD][0], w0);
            fadd2(acc[DD][1], w1);
        }
    }

    // collapse f32x2 halves, then butterfly-reduce over the 8 k-lanes
    float accf[DD + 1][2];
#pragma unroll
    for (int d = 0; d <= DD; d++) {
#pragma unroll
        for (int r = 0; r < 2; r++) {
            float v = lo32(acc[d][r]) + hi32(acc[d][r]);
            v += __shfl_xor_sync(0xffffffffu, v, 1);
            v += __shfl_xor_sync(0xffffffffu, v, 2);
            v += __shfl_xor_sync(0xffffffffu, v, 4);
            accf[d][r] = v;
        }
    }

    // fused epilogue: normalize, compat matmul, update, (softmax | output)
#pragma unroll
    for (int r = 0; r < 2; r++) {
        int m = m0 + r;
        float rinv = 1.0f / accf[DD][r];
        float sd[DD];
#pragma unroll
        for (int e = 0; e < DD; e++) sd[e] = accf[e][r] * rinv;

        float o[3];
#pragma unroll
        for (int j = 0; j < 3; j++) {
            int d = kk + 8 * j;
            if (d < DD) {
                float u = 0.f;
#pragma unroll
                for (int e = 0; e < DD; e++) u = fmaf(w_s[d * DD + e], sd[e], u);
                o[j] = seg[((size_t)(b * DD + d)) * NN + m] - u;
            } else {
                o[j] = -3.4e38f;
            }
        }

        if (last) {
#pragma unroll
            for (int j = 0; j < 3; j++) {
                int d = kk + 8 * j;
                if (d < DD) out[((size_t)(b * DD + d)) * NN + m] = o[j];
            }
        } else {
            float mx = fmaxf(o[0], fmaxf(o[1], o[2]));
            mx = fmaxf(mx, __shfl_xor_sync(0xffffffffu, mx, 1));
            mx = fmaxf(mx, __shfl_xor_sync(0xffffffffu, mx, 2));
            mx = fmaxf(mx, __shfl_xor_sync(0xffffffffu, mx, 4));
            float e3[3];
            float ssum = 0.f;
#pragma unroll
            for (int j = 0; j < 3; j++) {
                int d = kk + 8 * j;
                e3[j] = (d < DD) ? __expf(o[j] - mx) : 0.f;
                ssum += e3[j];
            }
            ssum += __shfl_xor_sync(0xffffffffu, ssum, 1);
            ssum += __shfl_xor_sync(0xffffffffu, ssum, 2);
            ssum += __shfl_xor_sync(0xffffffffu, ssum, 4);
            float si = 1.0f / ssum;
#pragma unroll
            for (int j = 0; j < 3; j++) {
                int d = kk + 8 * j;
                if (d < DD) Qout[((size_t)(b * DD + d)) * NN + m] = e3[j] * si;
            }
        }
    }
}

extern "C" void kernel_launch(void* const* d_in, const int* in_sizes, int n_in,
                              void* d_out, int out_size)
{
    const float* seg = nullptr;
    const float* W   = nullptr;
    const float* wts = nullptr;
    for (int i = 0; i < n_in; i++) {
        if (in_sizes[i] == BSZ * DD * NN)            seg = (const float*)d_in[i];
        else if (in_sizes[i] == BSZ * NN * NN)       W   = (const float*)d_in[i];
        else if (in_sizes[i] == DD * DD)             wts = (const float*)d_in[i];
    }

    softmax0_kernel<<<(BSZ * NN + 255) / 256, 256>>>(seg);
    for (int it = 0; it < NITERS; it++) {
        crf_main<<<BSZ * (NN / ROWS_PER_BLOCK), BLOCK>>>(
            seg, W, wts, (float*)d_out, it & 1, (it == NITERS - 1) ? 1 : 0);
    }
}

// round 4
// speedup vs baseline: 1.2181x; 1.2181x over previous
#include <cuda_runtime.h>
#include <math.h>

#define NN 4096          // n = 64*64
#define DD 21            // classes
#define BSZ 4            // batch
#define K_CH 256         // k chunk staged in smem
#define NCHUNK (NN / K_CH)
#define STEPS 8          // steps per chunk; each step covers 32 k per warp
#define BLOCK 128        // 4 warps
#define ROWS_PER_BLOCK 16
#define NITERS 5

typedef unsigned long long u64;

// Ping-pong softmax buffers (scratch via __device__ globals)
__device__ float g_QA[BSZ * DD * NN];
__device__ float g_QB[BSZ * DD * NN];

__device__ __forceinline__ void ffma2(u64 &acc, u64 a, u64 b) {
    asm("fma.rn.f32x2 %0, %1, %2, %0;" : "+l"(acc) : "l"(a), "l"(b));
}
__device__ __forceinline__ void fadd2(u64 &acc, u64 a) {
    asm("add.rn.f32x2 %0, %1, %0;" : "+l"(acc) : "l"(a));
}
__device__ __forceinline__ float lo32(u64 v) {
    return __uint_as_float((unsigned)(v & 0xffffffffull));
}
__device__ __forceinline__ float hi32(u64 v) {
    return __uint_as_float((unsigned)(v >> 32));
}
__device__ __forceinline__ unsigned smem_u32(const void* p) {
    return (unsigned)__cvta_generic_to_shared(p);
}
__device__ __forceinline__ void cp16(unsigned dst, const void* src) {
    asm volatile("cp.async.ca.shared.global [%0], [%1], 16;\n" :: "r"(dst), "l"(src));
}

// Initial softmax over class dim: g_QA = softmax(seg, axis=d)
__global__ void softmax0_kernel(const float* __restrict__ seg) {
    int idx = blockIdx.x * blockDim.x + threadIdx.x;
    if (idx >= BSZ * NN) return;
    int b = idx >> 12;
    int n = idx & (NN - 1);
    const float* p = seg + (size_t)b * DD * NN + n;
    float v[DD];
    float mx = -3.4e38f;
#pragma unroll
    for (int d = 0; d < DD; d++) { v[d] = p[(size_t)d * NN]; mx = fmaxf(mx, v[d]); }
    float s = 0.f;
#pragma unroll
    for (int d = 0; d < DD; d++) { v[d] = __expf(v[d] - mx); s += v[d]; }
    float si = 1.0f / s;
    float* q = g_QA + (size_t)b * DD * NN + n;
#pragma unroll
    for (int d = 0; d < DD; d++) q[(size_t)d * NN] = v[d] * si;
}

// One fused mean-field iteration.
__global__ __launch_bounds__(BLOCK, 5)
void crf_main(const float* __restrict__ seg,
              const float* __restrict__ W,
              const float* __restrict__ wts,
              float* __restrict__ out,
              int qsel, int last)
{
    __shared__ __align__(16) float q_s[2][DD][K_CH];
    __shared__ float w_s[DD * DD];

    const float* Qin  = qsel ? g_QB : g_QA;
    float*       Qout = qsel ? g_QA : g_QB;

    int tid  = threadIdx.x;
    int b    = blockIdx.x >> 8;          // 256 blocks per batch
    int mtil = blockIdx.x & 255;
    int warp = tid >> 5;
    int lane = tid & 31;
    int kk   = lane & 7;                 // k sub-lane (8)
    int mm   = lane >> 3;                // m group (4)
    int m    = mtil * ROWS_PER_BLOCK + warp * 4 + mm;

    for (int i = tid; i < DD * DD; i += BLOCK) w_s[i] = wts[i];

    const float* qg = Qin + (size_t)b * DD * NN;

    // stage chunk 0 (cp.async, 16B granules)
    {
        const float* src = qg;
        for (int i = tid; i < DD * (K_CH / 4); i += BLOCK) {
            int d = i >> 6;          // K_CH/4 = 64 per row
            int r = i & 63;
            cp16(smem_u32(&q_s[0][d][r * 4]), src + (size_t)d * NN + r * 4);
        }
        asm volatile("cp.async.commit_group;\n");
    }

    const float4* wp4 = (const float4*)(W + ((size_t)(b * NN + m)) * NN);

    // 4-deep W register prefetch queue. Global step t = c*STEPS + s consumes
    // float4 index t*8+kk. Queue slot = t & 3; since STEPS=8 is a multiple of
    // 4, t & 3 == s & 3 for every chunk (compile-time index under unroll).
    float4 wq[4];
    wq[0] = wp4[0 * 8 + kk];
    wq[1] = wp4[1 * 8 + kk];
    wq[2] = wp4[2 * 8 + kk];
    wq[3] = wp4[3 * 8 + kk];

    u64 acc[DD + 1];
#pragma unroll
    for (int d = 0; d <= DD; d++) acc[d] = 0ull;

    for (int c = 0; c < NCHUNK; c++) {
        if (c + 1 < NCHUNK) {
            const float* src = qg + (c + 1) * K_CH;
            int buf = (c + 1) & 1;
            for (int i = tid; i < DD * (K_CH / 4); i += BLOCK) {
                int d = i >> 6;
                int r = i & 63;
                cp16(smem_u32(&q_s[buf][d][r * 4]), src + (size_t)d * NN + r * 4);
            }
            asm volatile("cp.async.commit_group;\n");
            asm volatile("cp.async.wait_group 1;\n");
        } else {
            asm volatile("cp.async.wait_group 0;\n");
        }
        __syncthreads();

        const u64* qs2 = (const u64*)&q_s[c & 1][0][0];
#pragma unroll
        for (int s = 0; s < STEPS; s++) {
            int t = c * STEPS + s;
            float4 wv = wq[s & 3];
            int tn = t + 4; if (tn > 127) tn = 127;
            wq[s & 3] = wp4[tn * 8 + kk];

            u64 wa = ((const u64*)&wv)[0];
            u64 wb = ((const u64*)&wv)[1];
            int qi = s * 16 + kk * 2;        // u64 index within a Q row
#pragma unroll
            for (int d = 0; d < DD; d++) {
                const u64* qr = qs2 + d * (K_CH / 2);
                u64 qa = qr[qi];
                u64 qb = qr[qi + 1];
                ffma2(acc[d], qa, wa);
                ffma2(acc[d], qb, wb);
            }
            fadd2(acc[DD], wa);
            fadd2(acc[DD], wb);
        }
        __syncthreads();   // buf[c&1] will be overwritten two chunks later
    }

    // collapse f32x2 halves; butterfly over the 8 k-lanes
    float accf[DD + 1];
#pragma unroll
    for (int d = 0; d <= DD; d++) {
        float v = lo32(acc[d]) + hi32(acc[d]);
        v += __shfl_xor_sync(0xffffffffu, v, 1);
        v += __shfl_xor_sync(0xffffffffu, v, 2);
        v += __shfl_xor_sync(0xffffffffu, v, 4);
        accf[d] = v;
    }

    // fused epilogue: normalize, compat matmul, update, (softmax | output)
    float rinv = 1.0f / accf[DD];
    float sd[DD];
#pragma unroll
    for (int e = 0; e < DD; e++) sd[e] = accf[e] * rinv;

    float o[3];
#pragma unroll
    for (int j = 0; j < 3; j++) {
        int d = kk + 8 * j;
        if (d < DD) {
            float u = 0.f;
#pragma unroll
            for (int e = 0; e < DD; e++) u = fmaf(w_s[d * DD + e], sd[e], u);
            o[j] = seg[((size_t)(b * DD + d)) * NN + m] - u;
        } else {
            o[j] = -3.4e38f;
        }
    }

    if (last) {
#pragma unroll
        for (int j = 0; j < 3; j++) {
            int d = kk + 8 * j;
            if (d < DD) out[((size_t)(b * DD + d)) * NN + m] = o[j];
        }
    } else {
        float mx = fmaxf(o[0], fmaxf(o[1], o[2]));
        mx = fmaxf(mx, __shfl_xor_sync(0xffffffffu, mx, 1));
        mx = fmaxf(mx, __shfl_xor_sync(0xffffffffu, mx, 2));
        mx = fmaxf(mx, __shfl_xor_sync(0xffffffffu, mx, 4));
        float e3[3];
        float ssum = 0.f;
#pragma unroll
        for (int j = 0; j < 3; j++) {
            int d = kk + 8 * j;
            e3[j] = (d < DD) ? __expf(o[j] - mx) : 0.f;
            ssum += e3[j];
        }
        ssum += __shfl_xor_sync(0xffffffffu, ssum, 1);
        ssum += __shfl_xor_sync(0xffffffffu, ssum, 2);
        ssum += __shfl_xor_sync(0xffffffffu, ssum, 4);
        float si = 1.0f / ssum;
#pragma unroll
        for (int j = 0; j < 3; j++) {
            int d = kk + 8 * j;
            if (d < DD) Qout[((size_t)(b * DD + d)) * NN + m] = e3[j] * si;
        }
    }
}

extern "C" void kernel_launch(void* const* d_in, const int* in_sizes, int n_in,
                              void* d_out, int out_size)
{
    const float* seg = nullptr;
    const float* W   = nullptr;
    const float* wts = nullptr;
    for (int i = 0; i < n_in; i++) {
        if (in_sizes[i] == BSZ * DD * NN)            seg = (const float*)d_in[i];
        else if (in_sizes[i] == BSZ * NN * NN)       W   = (const float*)d_in[i];
        else if (in_sizes[i] == DD * DD)             wts = (const float*)d_in[i];
    }

    softmax0_kernel<<<(BSZ * NN + 255) / 256, 256>>>(seg);
    for (int it = 0; it < NITERS; it++) {
        crf_main<<<BSZ * (NN / ROWS_PER_BLOCK), BLOCK>>>(
            seg, W, wts, (float*)d_out, it & 1, (it == NITERS - 1) ? 1 : 0);
    }
}

// round 6
// speedup vs baseline: 3.0223x; 2.4811x over previous
#include <cuda_runtime.h>
#include <cstdint>
#include <math.h>

#define NN 4096
#define DD 21
#define BSZ 4
#define QR 48            // 24 hi (21 classes + ones + 2 pad) + 24 lo
#define MT 128           // m rows per block
#define KC 64            // k per staged chunk
#define NCH (NN / KC)    // 64
#define NITERS 5
#define THREADS 128
#define EP_PITCH 49

#define A_FLOATS (MT * KC)   // 8192
#define B_FLOATS (QR * KC)   // 3072
#define DSMEM_BYTES ((2 * A_FLOATS + 2 * B_FLOATS) * 4)   // 90112

// Q ping-pong buffers: [b][48][NN] fp32 (hi rows 0..23, lo rows 24..47)
__device__ float g_QA[BSZ * QR * NN];
__device__ float g_QB[BSZ * QR * NN];

__device__ __forceinline__ uint32_t smem_u32(const void* p) {
    return (uint32_t)__cvta_generic_to_shared(p);
}
__device__ __forceinline__ void cp16(uint32_t dst, const void* src) {
    asm volatile("cp.async.cg.shared.global [%0], [%1], 16;\n" :: "r"(dst), "l"(src));
}
__device__ __forceinline__ float trunc13(float x) {   // keep top 10 mantissa bits (tf32)
    return __uint_as_float(__float_as_uint(x) & 0xFFFFE000u);
}
// swizzled element index within a KC-float row: granule g (16B) XORed by row
__device__ __forceinline__ int swi(int row, int g, int e) {
    return row * KC + ((g ^ (row & 7)) << 2) + e;
}

// Initial softmax over class dim; hi/lo split + ones/pad rows into BOTH buffers.
__global__ void softmax0_kernel(const float* __restrict__ seg) {
    int idx = blockIdx.x * blockDim.x + threadIdx.x;
    if (idx >= BSZ * NN) return;
    int b = idx >> 12;
    int n = idx & (NN - 1);
    const float* p = seg + (size_t)b * DD * NN + n;
    float v[DD];
    float mx = -3.4e38f;
#pragma unroll
    for (int d = 0; d < DD; d++) { v[d] = p[(size_t)d * NN]; mx = fmaxf(mx, v[d]); }
    float s = 0.f;
#pragma unroll
    for (int d = 0; d < DD; d++) { v[d] = __expf(v[d] - mx); s += v[d]; }
    float si = 1.0f / s;
    float* qa = g_QA + (size_t)b * QR * NN + n;
    float* qb = g_QB + (size_t)b * QR * NN + n;
#pragma unroll
    for (int d = 0; d < DD; d++) {
        float q = v[d] * si;
        float h = trunc13(q);
        qa[(size_t)d * NN] = h;
        qa[(size_t)(24 + d) * NN] = q - h;
    }
    qa[21 * NN] = 1.0f; qa[22 * NN] = 0.f; qa[23 * NN] = 0.f;
    qa[45 * NN] = 0.f;  qa[46 * NN] = 0.f; qa[47 * NN] = 0.f;
    qb[21 * NN] = 1.0f; qb[22 * NN] = 0.f; qb[23 * NN] = 0.f;
    qb[45 * NN] = 0.f;  qb[46 * NN] = 0.f; qb[47 * NN] = 0.f;
}

// One fused mean-field iteration via mma.sync m16n8k8 tf32.
__global__ __launch_bounds__(THREADS, 2)
void crf_mma(const float* __restrict__ seg,
             const float* __restrict__ W,
             const float* __restrict__ wts,
             float* __restrict__ out,
             int qsel, int last)
{
    extern __shared__ float dsm[];
    __shared__ float w_s[DD * DD];

    float* A0 = dsm;
    float* A1 = dsm + A_FLOATS;
    float* B0 = dsm + 2 * A_FLOATS;
    float* B1 = dsm + 2 * A_FLOATS + B_FLOATS;
    float* ep = dsm;                 // reused after mainloop: [128][EP_PITCH]

    int tid  = threadIdx.x;
    int wid  = tid >> 5;
    int lane = tid & 31;
    int tg   = lane >> 2;            // 0..7
    int tig  = lane & 3;             // 0..3
    int b    = blockIdx.x >> 5;      // 32 m-tiles per batch
    int m0   = (blockIdx.x & 31) * MT;

    const float* Qin  = qsel ? g_QB : g_QA;
    float*       Qout = qsel ? g_QA : g_QB;
    const float* Wbase = W + ((size_t)(b * NN + m0)) * NN;
    const float* Qbase = Qin + (size_t)b * QR * NN;

    for (int i = tid; i < DD * DD; i += THREADS) w_s[i] = wts[i];

    // stage chunk kc into (Adst, Bdst); swizzled 16B granules
    auto stage = [&](float* Adst, float* Bdst, int kc) {
        uint32_t au = smem_u32(Adst);
#pragma unroll 4
        for (int i = tid; i < MT * (KC / 4); i += THREADS) {   // 2048 granules
            int row = i >> 4;
            int g   = i & 15;
            cp16(au + (uint32_t)(swi(row, g, 0) * 4),
                 Wbase + (size_t)row * NN + kc + g * 4);
        }
        uint32_t bu = smem_u32(Bdst);
        for (int i = tid; i < QR * (KC / 4); i += THREADS) {   // 768 granules
            int row = i >> 4;
            int g   = i & 15;
            cp16(bu + (uint32_t)(swi(row, g, 0) * 4),
                 Qbase + (size_t)row * NN + kc + g * 4);
        }
        asm volatile("cp.async.commit_group;\n");
    };

    stage(A0, B0, 0);
    stage(A1, B1, KC);

    float acc[2][6][4];
#pragma unroll
    for (int mt = 0; mt < 2; mt++)
#pragma unroll
        for (int nt = 0; nt < 6; nt++)
#pragma unroll
            for (int j = 0; j < 4; j++) acc[mt][nt][j] = 0.f;

    for (int c = 0; c < NCH; c++) {
        if (c == NCH - 1) asm volatile("cp.async.wait_group 0;\n" ::: "memory");
        else              asm volatile("cp.async.wait_group 1;\n" ::: "memory");
        __syncthreads();

        const float* Ab = (c & 1) ? A1 : A0;
        const float* Bq = (c & 1) ? B1 : B0;

#pragma unroll
        for (int s = 0; s < KC / 8; s++) {
            int g0 = s * 2;
            uint32_t a[2][4], bf[6][2];
#pragma unroll
            for (int mt = 0; mt < 2; mt++) {
                int m = wid * 32 + mt * 16 + tg;     // m&7 == tg
                const float* r0 = Ab + m * KC;
                const float* r8 = Ab + (m + 8) * KC; // (m+8)&7 == m&7
                int s0 = ((g0 ^ tg) << 2) + tig;
                int s1 = (((g0 + 1) ^ tg) << 2) + tig;
                a[mt][0] = __float_as_uint(r0[s0]);
                a[mt][1] = __float_as_uint(r8[s0]);
                a[mt][2] = __float_as_uint(r0[s1]);
                a[mt][3] = __float_as_uint(r8[s1]);
            }
#pragma unroll
            for (int nt = 0; nt < 6; nt++) {
                int d = nt * 8 + tg;                 // d&7 == tg
                const float* qr = Bq + d * KC;
                bf[nt][0] = __float_as_uint(qr[((g0 ^ tg) << 2) + tig]);
                bf[nt][1] = __float_as_uint(qr[(((g0 + 1) ^ tg) << 2) + tig]);
            }
#pragma unroll
            for (int mt = 0; mt < 2; mt++)
#pragma unroll
                for (int nt = 0; nt < 6; nt++) {
                    asm volatile(
                        "mma.sync.aligned.m16n8k8.row.col.f32.tf32.tf32.f32 "
                        "{%0,%1,%2,%3}, {%4,%5,%6,%7}, {%8,%9}, {%0,%1,%2,%3};"
                        : "+f"(acc[mt][nt][0]), "+f"(acc[mt][nt][1]),
                          "+f"(acc[mt][nt][2]), "+f"(acc[mt][nt][3])
                        : "r"(a[mt][0]), "r"(a[mt][1]), "r"(a[mt][2]), "r"(a[mt][3]),
                          "r"(bf[nt][0]), "r"(bf[nt][1]));
                }
        }
        __syncthreads();
        if (c + 2 < NCH) stage((c & 1) ? A1 : A0, (c & 1) ? B1 : B0, (c + 2) * KC);
    }

    // dump accumulators to smem so each thread can own one full m-row
    __syncthreads();
#pragma unroll
    for (int mt = 0; mt < 2; mt++) {
        int r = wid * 32 + mt * 16 + tg;
#pragma unroll
        for (int nt = 0; nt < 6; nt++) {
            int cc = nt * 8 + tig * 2;
            ep[r * EP_PITCH + cc]           = acc[mt][nt][0];
            ep[r * EP_PITCH + cc + 1]       = acc[mt][nt][1];
            ep[(r + 8) * EP_PITCH + cc]     = acc[mt][nt][2];
            ep[(r + 8) * EP_PITCH + cc + 1] = acc[mt][nt][3];
        }
    }
    __syncthreads();

    // epilogue: thread owns m-row = tid
    int m = m0 + tid;
    const float* row = ep + tid * EP_PITCH;
    float a2[DD + 1];
#pragma unroll
    for (int d = 0; d <= DD; d++) a2[d] = row[d] + row[24 + d];

    float rinv = 1.0f / a2[DD];       // rowsum via ones-row (col 21)
    float sd[DD];
#pragma unroll
    for (int e = 0; e < DD; e++) sd[e] = a2[e] * rinv;

    float o[DD];
#pragma unroll
    for (int d = 0; d < DD; d++) {
        float u = 0.f;
#pragma unroll
        for (int e = 0; e < DD; e++) u = fmaf(w_s[d * DD + e], sd[e], u);
        o[d] = seg[((size_t)(b * DD + d)) * NN + m] - u;
    }

    if (last) {
#pragma unroll
        for (int d = 0; d < DD; d++)
            out[((size_t)(b * DD + d)) * NN + m] = o[d];
    } else {
        float mx = -3.4e38f;
#pragma unroll
        for (int d = 0; d < DD; d++) mx = fmaxf(mx, o[d]);
        float ssum = 0.f;
        float ex[DD];
#pragma unroll
        for (int d = 0; d < DD; d++) { ex[d] = __expf(o[d] - mx); ssum += ex[d]; }
        float si = 1.0f / ssum;
        float* qo = Qout + (size_t)b * QR * NN + m;
#pragma unroll
        for (int d = 0; d < DD; d++) {
            float q = ex[d] * si;
            float h = trunc13(q);
            qo[(size_t)d * NN] = h;
            qo[(size_t)(24 + d) * NN] = q - h;
        }
    }
}

extern "C" void kernel_launch(void* const* d_in, const int* in_sizes, int n_in,
                              void* d_out, int out_size)
{
    const float* seg = nullptr;
    const float* W   = nullptr;
    const float* wts = nullptr;
    for (int i = 0; i < n_in; i++) {
        if (in_sizes[i] == BSZ * DD * NN)       seg = (const float*)d_in[i];
        else if (in_sizes[i] == BSZ * NN * NN)  W   = (const float*)d_in[i];
        else if (in_sizes[i] == DD * DD)        wts = (const float*)d_in[i];
    }

    cudaFuncSetAttribute(crf_mma, cudaFuncAttributeMaxDynamicSharedMemorySize,
                         DSMEM_BYTES);

    softmax0_kernel<<<(BSZ * NN + 255) / 256, 256>>>(seg);
    for (int it = 0; it < NITERS; it++) {
        crf_mma<<<BSZ * (NN / MT), THREADS, DSMEM_BYTES>>>(
            seg, W, wts, (float*)d_out, it & 1, (it == NITERS - 1) ? 1 : 0);
    }
}